// round 6
// baseline (speedup 1.0000x reference)
#include <cuda_runtime.h>

#define ALPHA_F 0.2f
#define EPS_F   1e-8f
#define MAXB    16

__device__ float        g_cls[MAXB];
__device__ float        g_reg[MAXB];
__device__ float        g_np[MAXB];
__device__ int          g_nv[MAXB];
__device__ unsigned int g_done = 0;

__device__ __forceinline__ float sqrt_ap(float x) {
    float y; asm("sqrt.approx.f32 %0, %1;" : "=f"(y) : "f"(x)); return y;
}

// negative focal term WITHOUT the (1-alpha) factor: x^1.5 * (-log(1-x))
__device__ __forceinline__ float neg_raw(float x) {
    return x * sqrt_ap(x) * (-__logf(1.0f - x));
}

struct ColdOut { float clsAdj; float accR; };

// Rare path (~1% of anchors): exact IoU argmax + positive-class focal term +
// smooth-L1 regression. __noinline__ keeps its registers out of the hot path.
__device__ __noinline__ ColdOut cold_pos(
    const float* __restrict__ cp, const float* __restrict__ rp,
    const float* __restrict__ anc, int a,
    const float4* s_box, const float* s_area, const float* s_lbl, int Mv)
{
    float4 ab = *reinterpret_cast<const float4*>(anc + (size_t)a * 4);
    float aw = ab.z - ab.x, ah = ab.w - ab.y;
    float areaA = aw * ah;

    float pb = -1.f, qb = 1.f;
    int   bm = 0;
    for (int m = 0; m < Mv; m++) {
        float4 g = s_box[m];
        float iw = fmaxf(fminf(ab.z, g.z) - fmaxf(ab.x, g.x), 0.f);
        float ih = fmaxf(fminf(ab.w, g.w) - fmaxf(ab.y, g.y), 0.f);
        float inter = iw * ih;
        float ua = fmaxf(areaA + s_area[m] - inter, EPS_F);
        if (inter * qb > pb * ua) { pb = inter; qb = ua; bm = m; }
    }
    int lbl = (int)s_lbl[bm];
    float x  = __ldg(cp + lbl);
    float om = 1.0f - x;

    ColdOut o;
    // replace the (1-alpha)-weighted negative term by the positive term
    o.clsAdj = ALPHA_F * om * sqrt_ap(om) * (-__logf(x)) - 0.8f * neg_raw(x);

    float acx = ab.x + 0.5f * aw, acy = ab.y + 0.5f * ah;
    float4 g = s_box[bm];
    float gwr = g.z - g.x, ghr = g.w - g.y;
    float gcx = g.x + 0.5f * gwr, gcy = g.y + 0.5f * ghr;
    float gw = fmaxf(gwr, 1.f), gh = fmaxf(ghr, 1.f);
    float t0 = ((gcx - acx) / aw) * 10.0f;
    float t1 = ((gcy - acy) / ah) * 10.0f;
    float t2 = __logf(gw / aw) * 5.0f;
    float t3 = __logf(gh / ah) * 5.0f;
    float4 r = *reinterpret_cast<const float4*>(rp);
    float d, s = 0.f;
    d = fabsf(t0 - r.x); s += (d <= (1.f / 9.f)) ? 4.5f * d * d : d - (0.5f / 9.f);
    d = fabsf(t1 - r.y); s += (d <= (1.f / 9.f)) ? 4.5f * d * d : d - (0.5f / 9.f);
    d = fabsf(t2 - r.z); s += (d <= (1.f / 9.f)) ? 4.5f * d * d : d - (0.5f / 9.f);
    d = fabsf(t3 - r.w); s += (d <= (1.f / 9.f)) ? 4.5f * d * d : d - (0.5f / 9.f);
    o.accR = s;
    return o;
}

__device__ __forceinline__ float cls_neg_sum(const float* __restrict__ cp, int C) {
    float s = 0.f;
    if (C == 20) {
        const float4* cp4 = reinterpret_cast<const float4*>(cp);
        float4 v0 = cp4[0], v1 = cp4[1], v2 = cp4[2], v3 = cp4[3], v4 = cp4[4];
        s += neg_raw(v0.x) + neg_raw(v0.y) + neg_raw(v0.z) + neg_raw(v0.w);
        s += neg_raw(v1.x) + neg_raw(v1.y) + neg_raw(v1.z) + neg_raw(v1.w);
        s += neg_raw(v2.x) + neg_raw(v2.y) + neg_raw(v2.z) + neg_raw(v2.w);
        s += neg_raw(v3.x) + neg_raw(v3.y) + neg_raw(v3.z) + neg_raw(v3.w);
        s += neg_raw(v4.x) + neg_raw(v4.y) + neg_raw(v4.z) + neg_raw(v4.w);
    } else {
        for (int c = 0; c < C; c++) s += neg_raw(cp[c]);
    }
    return s;
}

__global__ void __launch_bounds__(256, 5) fl_fused(
    const float* __restrict__ cls, const float* __restrict__ reg,
    const float* __restrict__ anc, const float* __restrict__ ann,
    float* __restrict__ out,
    int B, int A, int C, int M, unsigned int nblocks, int out_size)
{
    __shared__ float4 s_box[32];
    __shared__ float  s_area[32];
    __shared__ float  s_lbl[32];
    __shared__ int    s_mv;
    __shared__ float  s_red[3][8];

    const int tid = threadIdx.x;
    const int b   = blockIdx.y;
    const int a0  = blockIdx.x * 512 + tid;
    const int a1  = a0 + 256;

    // ---- warp 0: load GT, compact valid entries (order-preserving) ----
    if (tid < 32) {
        int cnt = 0;
        for (int base = 0; base < M; base += 32) {
            int m = base + tid;
            float x1 = 0, y1 = 0, x2 = 0, y2 = 0, lb = -1.0f;
            if (m < M) {
                const float* p = ann + ((size_t)b * M + m) * 5;
                x1 = p[0]; y1 = p[1]; x2 = p[2]; y2 = p[3]; lb = p[4];
            }
            bool v = (lb != -1.0f);
            unsigned msk = __ballot_sync(0xffffffffu, v);
            if (v) {
                int pos = cnt + __popc(msk & ((1u << tid) - 1u));
                s_box[pos]  = make_float4(x1, y1, x2, y2);
                s_area[pos] = (x2 - x1) * (y2 - y1);
                s_lbl[pos]  = lb;
            }
            cnt += __popc(msk);
        }
        if (tid == 0) s_mv = cnt;
    }
    __syncthreads();

    const int Mv = s_mv;
    if (blockIdx.x == 0 && tid == 0) g_nv[b] = Mv;

    float accC = 0.f, accR = 0.f, np = 0.f;
    if (Mv > 0) {
        const bool act0 = (a0 < A);
        const bool act1 = (a1 < A);

        float4 ab0 = make_float4(0, 0, 0, 0), ab1 = make_float4(0, 0, 0, 0);
        float areaA0 = 3.4e38f, areaA1 = 3.4e38f;  // huge => thresholds never fire
        if (act0) {
            ab0 = *reinterpret_cast<const float4*>(anc + (size_t)a0 * 4);
            areaA0 = (ab0.z - ab0.x) * (ab0.w - ab0.y);
        }
        if (act1) {
            ab1 = *reinterpret_cast<const float4*>(anc + (size_t)a1 * 4);
            areaA1 = (ab1.z - ab1.x) * (ab1.w - ab1.y);
        }

        // ---- threshold keys, areaA hoisted out of the loop ----
        // pos    <=>  max_m (3.0*inter_m - areaB_m) >= areaA
        // band   <=>  max_m (3.5*inter_m - areaB_m) >= areaA
        // single-clamp inter: if either extent is negative, inter <= 0 and the
        // key is <= -areaB < 0 <= areaA, so it can never fire a threshold.
        float pK0 = -1.f, iK0 = -1.f, pK1 = -1.f, iK1 = -1.f;
        #pragma unroll 4
        for (int m = 0; m < Mv; m++) {
            float4 g  = s_box[m];
            float  ar = s_area[m];
            {
                float iw = fminf(ab0.z, g.z) - fmaxf(ab0.x, g.x);
                float ih = fminf(ab0.w, g.w) - fmaxf(ab0.y, g.y);
                float inter = fmaxf(iw, 0.f) * ih;
                pK0 = fmaxf(pK0, fmaf(3.0f, inter, -ar));
                iK0 = fmaxf(iK0, fmaf(3.5f, inter, -ar));
            }
            {
                float iw = fminf(ab1.z, g.z) - fmaxf(ab1.x, g.x);
                float ih = fminf(ab1.w, g.w) - fmaxf(ab1.y, g.y);
                float inter = fmaxf(iw, 0.f) * ih;
                pK1 = fmaxf(pK1, fmaf(3.0f, inter, -ar));
                iK1 = fmaxf(iK1, fmaf(3.5f, inter, -ar));
            }
        }
        bool pos0 = (pK0 >= areaA0);
        bool pos1 = (pK1 >= areaA1);
        bool ign0 = (!pos0) && (iK0 >= areaA0);
        bool ign1 = (!pos1) && (iK1 >= areaA1);

        const size_t rowb = (size_t)b * A;
        const float* cp0 = cls + (rowb + a0) * (size_t)C;
        const float* cp1 = cls + (rowb + a1) * (size_t)C;

        float negS = 0.f;
        if (act0 && !ign0) negS += cls_neg_sum(cp0, C);
        if (act1 && !ign1) negS += cls_neg_sum(cp1, C);
        accC = 0.8f * negS;

        if (pos0) {
            ColdOut c = cold_pos(cp0, reg + (rowb + a0) * 4, anc, a0,
                                 s_box, s_area, s_lbl, Mv);
            accC += c.clsAdj; accR += c.accR; np += 1.f;
        }
        if (pos1) {
            ColdOut c = cold_pos(cp1, reg + (rowb + a1) * 4, anc, a1,
                                 s_box, s_area, s_lbl, Mv);
            accC += c.clsAdj; accR += c.accR; np += 1.f;
        }
    }

    // ---- block reduction ----
    #pragma unroll
    for (int o = 16; o > 0; o >>= 1) {
        accC += __shfl_down_sync(0xffffffffu, accC, o);
        accR += __shfl_down_sync(0xffffffffu, accR, o);
        np   += __shfl_down_sync(0xffffffffu, np,   o);
    }
    if ((tid & 31) == 0) {
        int w = tid >> 5;
        s_red[0][w] = accC; s_red[1][w] = accR; s_red[2][w] = np;
    }
    __syncthreads();

    if (tid == 0) {
        float bc = 0.f, br = 0.f, bn = 0.f;
        for (int w = 0; w < 8; w++) { bc += s_red[0][w]; br += s_red[1][w]; bn += s_red[2][w]; }
        atomicAdd(&g_cls[b], bc);
        atomicAdd(&g_reg[b], br);
        atomicAdd(&g_np[b],  bn);
        __threadfence();
        unsigned int d = atomicAdd(&g_done, 1u);
        if (d == nblocks - 1u) {
            // last block: finalize, write output, reset state for graph replay
            float cs = 0.f, rs = 0.f;
            for (int bb = 0; bb < B; bb++) {
                float npv = atomicExch(&g_np[bb],  0.f);
                float clv = atomicExch(&g_cls[bb], 0.f);
                float rlv = atomicExch(&g_reg[bb], 0.f);
                int   nv  = atomicAdd(&g_nv[bb], 0);
                float cl = clv / fmaxf(npv, 1.f);
                float rl = (npv > 0.f) ? rlv / (4.f * npv) : 0.f;
                if (nv == 0) { cl = 0.f; rl = 0.f; }
                cs += cl; rs += rl;
            }
            out[0] = cs / (float)B;
            if (out_size > 1) out[1] = rs / (float)B;
            g_done = 0;
        }
    }
}

extern "C" void kernel_launch(void* const* d_in, const int* in_sizes, int n_in,
                              void* d_out, int out_size)
{
    const float* cls = (const float*)d_in[0];
    const float* reg = (const float*)d_in[1];
    const float* anc = (const float*)d_in[2];
    const float* ann = (const float*)d_in[3];

    int A = in_sizes[2] / 4;                 // anchors [1,A,4]
    int B = in_sizes[1] / (4 * A);           // regressions [B,A,4]
    int C = in_sizes[0] / B / A;             // classifications [B,A,C]
    int M = in_sizes[3] / (5 * B);           // annotations [B,M,5]

    dim3 grid((A + 511) / 512, B);
    unsigned int nblocks = grid.x * grid.y;
    fl_fused<<<grid, 256>>>(cls, reg, anc, ann, (float*)d_out,
                            B, A, C, M, nblocks, out_size);
}

// round 9
// speedup vs baseline: 1.5144x; 1.5144x over previous
#include <cuda_runtime.h>

#define ALPHA_F 0.2f
#define EPS_F   1e-8f
#define MAXB    16

__device__ float        g_cls[MAXB];
__device__ float        g_reg[MAXB];
__device__ float        g_np[MAXB];
__device__ int          g_nv[MAXB];
__device__ unsigned int g_done = 0;

__device__ __forceinline__ float sqrt_ap(float x) {
    float y; asm("sqrt.approx.f32 %0, %1;" : "=f"(y) : "f"(x)); return y;
}

// negative focal term WITHOUT the (1-alpha) factor: x^1.5 * (-log(1-x))
__device__ __forceinline__ float neg_raw(float x) {
    return x * sqrt_ap(x) * (-__logf(1.0f - x));
}

__global__ void __launch_bounds__(256) fl_fused(
    const float* __restrict__ cls, const float* __restrict__ reg,
    const float* __restrict__ anc, const float* __restrict__ ann,
    float* __restrict__ out,
    int B, int A, int C, int M, unsigned int nblocks, int out_size)
{
    __shared__ float4 s_box[32];
    __shared__ float  s_arS[32];   // areaB / 3.5  (1e30 for padding slots)
    __shared__ float  s_area[32];  // raw areaB    (candidate path)
    __shared__ float  s_lbl[32];
    __shared__ int    s_mv;
    __shared__ float  s_red[3][8];

    const int tid = threadIdx.x;
    const int b   = blockIdx.y;
    const int a   = blockIdx.x * blockDim.x + tid;

    // ---- warp 0: init padding, load GT, compact valid entries ----
    if (tid < 32) {
        s_box[tid]  = make_float4(0.f, 0.f, 0.f, 0.f);
        s_arS[tid]  = 1e30f;
        s_area[tid] = 0.f;
        s_lbl[tid]  = -1.f;
        __syncwarp();
        int cnt = 0;
        for (int base = 0; base < M; base += 32) {
            int m = base + tid;
            float x1 = 0, y1 = 0, x2 = 0, y2 = 0, lb = -1.0f;
            if (m < M) {
                const float* p = ann + ((size_t)b * M + m) * 5;
                x1 = p[0]; y1 = p[1]; x2 = p[2]; y2 = p[3]; lb = p[4];
            }
            bool v = (lb != -1.0f);
            unsigned msk = __ballot_sync(0xffffffffu, v);
            if (v) {
                int pos = cnt + __popc(msk & ((1u << tid) - 1u));
                if (pos < 32) {
                    float ar = (x2 - x1) * (y2 - y1);
                    s_box[pos]  = make_float4(x1, y1, x2, y2);
                    s_arS[pos]  = ar * (1.0f / 3.5f);
                    s_area[pos] = ar;
                    s_lbl[pos]  = lb;
                }
            }
            cnt += __popc(msk);
        }
        if (tid == 0) s_mv = cnt;
    }
    __syncthreads();

    const int Mv = s_mv;
    if (blockIdx.x == 0 && tid == 0) g_nv[b] = Mv;

    float accC = 0.f, accR = 0.f, np = 0.f;
    if (a < A && Mv > 0) {
        float4 ab = *reinterpret_cast<const float4*>(anc + (size_t)a * 4);
        const float areaA = (ab.z - ab.x) * (ab.w - ab.y);
        const float aS    = areaA * (1.0f / 3.5f);

        // ---- hot loop: single band-key (iou >= 0.4 candidate test) ----
        // iou >= 0.4  <=>  3.5*inter >= areaA + areaB
        //             <=>  inter - areaB/3.5 >= areaA/3.5
        // single-clamp inter: a negative extent makes the key <= -areaB/3.5 < aS.
        float kM = -3.4e38f;
        #pragma unroll
        for (int m = 0; m < 32; m++) {
            float4 g = s_box[m];
            float iw = fminf(ab.z, g.z) - fmaxf(ab.x, g.x);
            float ih = fminf(ab.w, g.w) - fmaxf(ab.y, g.y);
            float inter = fmaxf(iw, 0.f) * ih;
            kM = fmaxf(kM, inter - s_arS[m]);
        }
        const bool cand = (kM >= aS);

        // ---- candidate path (~3%): exact pos test + IoU argmax ----
        bool pos = false;
        int  bm  = 0;
        if (cand) {
            float pK = -3.4e38f;
            float pb = -1.f, qb = 1.f;
            for (int m = 0; m < Mv; m++) {
                float4 g = s_box[m];
                float iw = fmaxf(fminf(ab.z, g.z) - fmaxf(ab.x, g.x), 0.f);
                float ih = fmaxf(fminf(ab.w, g.w) - fmaxf(ab.y, g.y), 0.f);
                float inter = iw * ih;
                float S  = areaA + s_area[m];
                float ua = fmaxf(S - inter, EPS_F);
                pK = fmaxf(pK, fmaf(3.0f, inter, -S));   // iou>=0.5 <=> 3*inter>=S
                if (inter * qb > pb * ua) { pb = inter; qb = ua; bm = m; }
            }
            pos = (pK >= 0.f);
        }
        const bool ignore = cand && !pos;

        if (!ignore) {
            // ---- classification focal loss (all-negative pass; inputs are
            //      probabilities in (0,1), EPS clamp is an identity) ----
            const float* cp = cls + ((size_t)b * A + a) * (size_t)C;
            float negS = 0.f;
            if (C == 20) {
                const float4* cp4 = reinterpret_cast<const float4*>(cp);
                float4 v0 = cp4[0], v1 = cp4[1], v2 = cp4[2], v3 = cp4[3], v4 = cp4[4];
                negS += neg_raw(v0.x) + neg_raw(v0.y) + neg_raw(v0.z) + neg_raw(v0.w);
                negS += neg_raw(v1.x) + neg_raw(v1.y) + neg_raw(v1.z) + neg_raw(v1.w);
                negS += neg_raw(v2.x) + neg_raw(v2.y) + neg_raw(v2.z) + neg_raw(v2.w);
                negS += neg_raw(v3.x) + neg_raw(v3.y) + neg_raw(v3.z) + neg_raw(v3.w);
                negS += neg_raw(v4.x) + neg_raw(v4.y) + neg_raw(v4.z) + neg_raw(v4.w);
            } else {
                for (int c = 0; c < C; c++) negS += neg_raw(cp[c]);
            }
            accC = 0.8f * negS;

            if (pos) {
                int lbl = (int)s_lbl[bm];
                float x = __ldg(cp + lbl);
                accC -= 0.8f * neg_raw(x);                          // undo negative term
                float om = 1.0f - x;
                accC += ALPHA_F * om * sqrt_ap(om) * (-__logf(x));  // positive term

                // ---- regression smooth-L1 ----
                np = 1.f;
                float aw = ab.z - ab.x, ah = ab.w - ab.y;
                float acx = ab.x + 0.5f * aw, acy = ab.y + 0.5f * ah;
                float4 g = s_box[bm];
                float gwr = g.z - g.x, ghr = g.w - g.y;
                float gcx = g.x + 0.5f * gwr, gcy = g.y + 0.5f * ghr;
                float gw = fmaxf(gwr, 1.f), gh = fmaxf(ghr, 1.f);
                float t0 = ((gcx - acx) / aw) * 10.0f;
                float t1 = ((gcy - acy) / ah) * 10.0f;
                float t2 = __logf(gw / aw) * 5.0f;
                float t3 = __logf(gh / ah) * 5.0f;
                float4 r = *reinterpret_cast<const float4*>(reg + ((size_t)b * A + a) * 4);
                float d, s = 0.f;
                d = fabsf(t0 - r.x); s += (d <= (1.f / 9.f)) ? 4.5f * d * d : d - (0.5f / 9.f);
                d = fabsf(t1 - r.y); s += (d <= (1.f / 9.f)) ? 4.5f * d * d : d - (0.5f / 9.f);
                d = fabsf(t2 - r.z); s += (d <= (1.f / 9.f)) ? 4.5f * d * d : d - (0.5f / 9.f);
                d = fabsf(t3 - r.w); s += (d <= (1.f / 9.f)) ? 4.5f * d * d : d - (0.5f / 9.f);
                accR = s;
            }
        }
    }

    // ---- block reduction ----
    #pragma unroll
    for (int o = 16; o > 0; o >>= 1) {
        accC += __shfl_down_sync(0xffffffffu, accC, o);
        accR += __shfl_down_sync(0xffffffffu, accR, o);
        np   += __shfl_down_sync(0xffffffffu, np,   o);
    }
    if ((tid & 31) == 0) {
        int w = tid >> 5;
        s_red[0][w] = accC; s_red[1][w] = accR; s_red[2][w] = np;
    }
    __syncthreads();

    if (tid == 0) {
        float bc = 0.f, br = 0.f, bn = 0.f;
        for (int w = 0; w < 8; w++) { bc += s_red[0][w]; br += s_red[1][w]; bn += s_red[2][w]; }
        atomicAdd(&g_cls[b], bc);
        atomicAdd(&g_reg[b], br);
        atomicAdd(&g_np[b],  bn);
        __threadfence();
        unsigned int d = atomicAdd(&g_done, 1u);
        if (d == nblocks - 1u) {
            // last block: finalize, write output, reset state for graph replay
            float cs = 0.f, rs = 0.f;
            for (int bb = 0; bb < B; bb++) {
                float npv = atomicExch(&g_np[bb],  0.f);
                float clv = atomicExch(&g_cls[bb], 0.f);
                float rlv = atomicExch(&g_reg[bb], 0.f);
                int   nv  = atomicAdd(&g_nv[bb], 0);
                float cl = clv / fmaxf(npv, 1.f);
                float rl = (npv > 0.f) ? rlv / (4.f * npv) : 0.f;
                if (nv == 0) { cl = 0.f; rl = 0.f; }
                cs += cl; rs += rl;
            }
            out[0] = cs / (float)B;
            if (out_size > 1) out[1] = rs / (float)B;
            g_done = 0;
        }
    }
}

extern "C" void kernel_launch(void* const* d_in, const int* in_sizes, int n_in,
                              void* d_out, int out_size)
{
    const float* cls = (const float*)d_in[0];
    const float* reg = (const float*)d_in[1];
    const float* anc = (const float*)d_in[2];
    const float* ann = (const float*)d_in[3];

    int A = in_sizes[2] / 4;                 // anchors [1,A,4]
    int B = in_sizes[1] / (4 * A);           // regressions [B,A,4]
    int C = in_sizes[0] / B / A;             // classifications [B,A,C]
    int M = in_sizes[3] / (5 * B);           // annotations [B,M,5]

    int threads = 256;
    dim3 grid((A + threads - 1) / threads, B);
    unsigned int nblocks = grid.x * grid.y;
    fl_fused<<<grid, threads>>>(cls, reg, anc, ann, (float*)d_out,
                                B, A, C, M, nblocks, out_size);
}